// round 14
// baseline (speedup 1.0000x reference)
#include <cuda_runtime.h>
#include <cuda_bf16.h>
#include <cstdint>

#define HID 20
#define NT 256
#define AHEAD (152 * 6)   // one full wave ahead (152 SMs x 6 CTAs/SM)

// Transformed-weight layout (261 floats):
//   [0]   wi_g*0.5   [20] wi_p*0.5  [40] (b_ih+b_hh)_i*0.5
//   [60]  wg_g       [80] wg_p      [100] (b)_g
//   [120] wo_g*0.5   [140] wo_p*0.5 [160] (b)_o*0.5
//   [180] wf_g*0.5   [200] wf_p*0.5 [220] (b)_f*0.5
//   [240] W_out      [260] b_out
#define CW_SIZE 261
__constant__ float cW[CW_SIZE];

__device__ __forceinline__ float tanh_ap(float x) {
    float y;
    asm("tanh.approx.f32 %0, %1;" : "=f"(y) : "f"(x));
    return y;
}
// sigmoid(z) where zh = 0.5*z was computed with pre-halved weights
__device__ __forceinline__ float sig_from_half(float zh) {
    return fmaf(0.5f, tanh_ap(zh), 0.5f);
}

// Writes transformed weights directly into cW's backing store.
// Signals dependent launch immediately: the main grid's prologue and its
// cW-independent loads overlap with this kernel's execution (PDL).
__global__ void prep_kernel(const float* __restrict__ W_ih,
                            const float* __restrict__ b_ih,
                            const float* __restrict__ b_hh,
                            const float* __restrict__ W_out,
                            const float* __restrict__ b_out,
                            float* __restrict__ cw)
{
    asm volatile("griddepcontrol.launch_dependents;" ::: "memory");
    const int k = threadIdx.x;
    if (k < HID) {
        const int rf = 20 + k, rg = 40 + k, ro = 60 + k;
        cw[k]        = 0.5f * W_ih[2 * k];
        cw[20 + k]   = 0.5f * W_ih[2 * k + 1];
        cw[40 + k]   = 0.5f * (b_ih[k] + b_hh[k]);
        cw[60 + k]   = W_ih[2 * rg];
        cw[80 + k]   = W_ih[2 * rg + 1];
        cw[100 + k]  = b_ih[rg] + b_hh[rg];
        cw[120 + k]  = 0.5f * W_ih[2 * ro];
        cw[140 + k]  = 0.5f * W_ih[2 * ro + 1];
        cw[160 + k]  = 0.5f * (b_ih[ro] + b_hh[ro]);
        cw[180 + k]  = 0.5f * W_ih[2 * rf];
        cw[200 + k]  = 0.5f * W_ih[2 * rf + 1];
        cw[220 + k]  = 0.5f * (b_ih[rf] + b_hh[rf]);
        cw[240 + k]  = W_out[k];
    }
    if (k == 0) cw[260] = b_out[0];
}

__device__ __forceinline__ void griddep_wait() {
    asm volatile("griddepcontrol.wait;" ::: "memory");
}

__global__ void __launch_bounds__(NT, 6)
lstm_opt_kernel(const float* __restrict__ params,
                const float* __restrict__ grads,
                const float* __restrict__ h0,
                const float* __restrict__ c0,
                const float* __restrict__ W_hh,   // cold general path
                float* __restrict__ out,
                int n)
{
    const int t    = threadIdx.x;
    const int i    = blockIdx.x * NT + t;
    const int lane = t & 31;

    // ---- L2 prefetch for the tile one wave ahead (same SM slot next wave).
    // No destination register, no scoreboard: pure pipeline deepening.
    {
        const long long pbase = (long long)(blockIdx.x + AHEAD) * NT;
        if (pbase < n) {
            const int prows  = min(NT, n - (int)pbase);
            const int pbytes = prows * (HID * 4);           // tile bytes (<=20480)
            const int off    = t * 128;                     // one 128B line per thread
            if (off < pbytes) {
                const char* pc = reinterpret_cast<const char*>(c0 + pbase * HID) + off;
                const char* ph = reinterpret_cast<const char*>(h0 + pbase * HID) + off;
                asm volatile("prefetch.global.L2 [%0];" :: "l"(pc));
                asm volatile("prefetch.global.L2 [%0];" :: "l"(ph));
            }
        }
    }

    // Warp's 32-coordinate block: coords [wbase, wbase+32)
    const int wbase = i - lane;
    const bool full_warp = (wbase + 32 <= n);

    if (full_warp) {
        // ---- cW-independent phase: runs BEFORE the PDL wait ----
        const float g = __ldg(&grads[i]);
        const float p = __ldg(&params[i]);

        // Coalesced bitwise-zero scan of the warp's c0 and h0 blocks:
        // interleaved c/h loads with independent OR accumulators -> two
        // address streams, shallow dependency chains, streaming (evict-first)
        // cache policy since these bytes are touched exactly once.
        const uint4* c4 = reinterpret_cast<const uint4*>(c0 + (size_t)wbase * HID);
        const uint4* h4 = reinterpret_cast<const uint4*>(h0 + (size_t)wbase * HID);
        uint32_t orc = 0u, orh = 0u;
        #pragma unroll
        for (int q = 0; q < 5; q++) {
            uint4 vc = __ldcs(&c4[lane + 32 * q]);
            uint4 vh = __ldcs(&h4[lane + 32 * q]);
            orc |= vc.x | vc.y | vc.z | vc.w;
            orh |= vh.x | vh.y | vh.z | vh.w;
        }
        // All bits zero across the warp => every c0/h0 value is +0.0f
        // => f*c0 == 0 and the W_hh matvec is exactly zero. Warp-uniform.
        const bool allzero = __all_sync(0xffffffffu, (orc | orh) == 0u);

        // prep grid's cW writes must be visible beyond this point
        griddep_wait();

        if (__builtin_expect(allzero, 1)) {
            // ---- fast path: no cv, no h; weights are constant-bank operands ----
            float acc = cW[260];
            #pragma unroll
            for (int k = 0; k < HID; k++) {
                float zi = fmaf(cW[k],       g, fmaf(cW[20 + k],  p, cW[40 + k]));  // halved
                float zg = fmaf(cW[60 + k],  g, fmaf(cW[80 + k],  p, cW[100 + k]));
                float zo = fmaf(cW[120 + k], g, fmaf(cW[140 + k], p, cW[160 + k])); // halved

                float ik = sig_from_half(zi);
                float gk = tanh_ap(zg);
                float ok = sig_from_half(zo);

                float c1 = ik * gk;                       // f*c0 == 0, i*g only
                acc = fmaf(ok * tanh_ap(c1), cW[240 + k], acc);
            }
            __stcs(&out[i], acc);
            return;
        }

        // ---- general path (warp-uniform, cold): full LSTM incl. W_hh matvec ----
        float cv[HID], hv[HID];
        {
            const float4* cr = reinterpret_cast<const float4*>(c0 + (size_t)i * HID);
            const float4* hr = reinterpret_cast<const float4*>(h0 + (size_t)i * HID);
            #pragma unroll
            for (int q = 0; q < 5; q++) {
                float4 cc = cr[q];
                cv[4 * q + 0] = cc.x; cv[4 * q + 1] = cc.y;
                cv[4 * q + 2] = cc.z; cv[4 * q + 3] = cc.w;
                float4 hh = hr[q];
                hv[4 * q + 0] = hh.x; hv[4 * q + 1] = hh.y;
                hv[4 * q + 2] = hh.z; hv[4 * q + 3] = hh.w;
            }
        }
        float acc = cW[260];
        #pragma unroll 1
        for (int k = 0; k < HID; k++) {
            float zi = fmaf(cW[k],       g, fmaf(cW[20 + k],  p, cW[40 + k]));
            float zg = fmaf(cW[60 + k],  g, fmaf(cW[80 + k],  p, cW[100 + k]));
            float zo = fmaf(cW[120 + k], g, fmaf(cW[140 + k], p, cW[160 + k]));
            float zf = fmaf(cW[180 + k], g, fmaf(cW[200 + k], p, cW[220 + k]));
            const int ri = k, rf = 20 + k, rg = 40 + k, ro = 60 + k;
            #pragma unroll 1
            for (int m = 0; m < HID; m++) {
                float hm = hv[m];
                zi = fmaf(0.5f * __ldg(&W_hh[ri * HID + m]), hm, zi);
                zf = fmaf(0.5f * __ldg(&W_hh[rf * HID + m]), hm, zf);
                zg = fmaf(       __ldg(&W_hh[rg * HID + m]), hm, zg);
                zo = fmaf(0.5f * __ldg(&W_hh[ro * HID + m]), hm, zo);
            }
            float ik = sig_from_half(zi);
            float fk = sig_from_half(zf);
            float gk = tanh_ap(zg);
            float ok = sig_from_half(zo);
            float c1 = fmaf(fk, cv[k], ik * gk);
            acc = fmaf(ok * tanh_ap(c1), cW[240 + k], acc);
        }
        out[i] = acc;
        return;
    }

    // ---- boundary warp (partial): per-thread general path with guards ----
    if (i >= n) { griddep_wait(); return; }
    {
        const float g = grads[i];
        const float p = params[i];
        float cv[HID], hv[HID];
        #pragma unroll
        for (int m = 0; m < HID; m++) {
            cv[m] = c0[(size_t)i * HID + m];
            hv[m] = h0[(size_t)i * HID + m];
        }
        griddep_wait();
        float acc = cW[260];
        #pragma unroll 1
        for (int k = 0; k < HID; k++) {
            float zi = fmaf(cW[k],       g, fmaf(cW[20 + k],  p, cW[40 + k]));
            float zg = fmaf(cW[60 + k],  g, fmaf(cW[80 + k],  p, cW[100 + k]));
            float zo = fmaf(cW[120 + k], g, fmaf(cW[140 + k], p, cW[160 + k]));
            float zf = fmaf(cW[180 + k], g, fmaf(cW[200 + k], p, cW[220 + k]));
            const int ri = k, rf = 20 + k, rg = 40 + k, ro = 60 + k;
            #pragma unroll 1
            for (int m = 0; m < HID; m++) {
                float hm = hv[m];
                zi = fmaf(0.5f * __ldg(&W_hh[ri * HID + m]), hm, zi);
                zf = fmaf(0.5f * __ldg(&W_hh[rf * HID + m]), hm, zf);
                zg = fmaf(       __ldg(&W_hh[rg * HID + m]), hm, zg);
                zo = fmaf(0.5f * __ldg(&W_hh[ro * HID + m]), hm, zo);
            }
            float ik = sig_from_half(zi);
            float fk = sig_from_half(zf);
            float gk = tanh_ap(zg);
            float ok = sig_from_half(zo);
            float c1 = fmaf(fk, cv[k], ik * gk);
            acc = fmaf(ok * tanh_ap(c1), cW[240 + k], acc);
        }
        out[i] = acc;
    }
}

extern "C" void kernel_launch(void* const* d_in, const int* in_sizes, int n_in,
                              void* d_out, int out_size)
{
    const float* params = (const float*)d_in[0];
    const float* grads  = (const float*)d_in[1];
    const float* h0     = (const float*)d_in[2];
    const float* c0     = (const float*)d_in[3];
    const float* W_ih   = (const float*)d_in[4];
    const float* W_hh   = (const float*)d_in[5];
    const float* b_ih   = (const float*)d_in[6];
    const float* b_hh   = (const float*)d_in[7];
    const float* W_out  = (const float*)d_in[8];
    const float* b_out  = (const float*)d_in[9];
    float* out = (float*)d_out;

    int n = in_sizes[0];

    void* cw_ptr = nullptr;
    cudaGetSymbolAddress(&cw_ptr, cW);     // host-side query, capture-safe
    prep_kernel<<<1, 32>>>(W_ih, b_ih, b_hh, W_out, b_out, (float*)cw_ptr);

    // Main kernel with Programmatic Stream Serialization: launches while prep
    // is still executing; griddepcontrol.wait inside orders cW consumption.
    int blocks = (n + NT - 1) / NT;

    cudaLaunchConfig_t cfg = {};
    cfg.gridDim  = dim3((unsigned)blocks, 1, 1);
    cfg.blockDim = dim3(NT, 1, 1);
    cfg.dynamicSmemBytes = 0;
    cfg.stream = 0;
    cudaLaunchAttribute attrs[1];
    attrs[0].id = cudaLaunchAttributeProgrammaticStreamSerialization;
    attrs[0].val.programmaticStreamSerializationAllowed = 1;
    cfg.attrs = attrs;
    cfg.numAttrs = 1;

    cudaLaunchKernelEx(&cfg, lstm_opt_kernel,
                       params, grads, h0, c0, W_hh, out, n);
}

// round 15
// speedup vs baseline: 1.2420x; 1.2420x over previous
#include <cuda_runtime.h>
#include <cuda_bf16.h>
#include <cstdint>

#define HID 20
#define NT 256

// Transformed-weight layout (261 floats):
//   [0]   wi_g*0.5   [20] wi_p*0.5  [40] (b_ih+b_hh)_i*0.5
//   [60]  wg_g       [80] wg_p      [100] (b)_g
//   [120] wo_g*0.5   [140] wo_p*0.5 [160] (b)_o*0.5
//   [180] wf_g*0.5   [200] wf_p*0.5 [220] (b)_f*0.5
//   [240] W_out      [260] b_out
#define CW_SIZE 261
__constant__ float cW[CW_SIZE];

__device__ __forceinline__ float tanh_ap(float x) {
    float y;
    asm("tanh.approx.f32 %0, %1;" : "=f"(y) : "f"(x));
    return y;
}
// sigmoid(z) where zh = 0.5*z was computed with pre-halved weights
__device__ __forceinline__ float sig_from_half(float zh) {
    return fmaf(0.5f, tanh_ap(zh), 0.5f);
}

// Writes transformed weights directly into cW's backing store.
// Signals dependent launch immediately: the main grid's prologue and its
// cW-independent loads overlap with this kernel's execution (PDL).
__global__ void prep_kernel(const float* __restrict__ W_ih,
                            const float* __restrict__ b_ih,
                            const float* __restrict__ b_hh,
                            const float* __restrict__ W_out,
                            const float* __restrict__ b_out,
                            float* __restrict__ cw)
{
    asm volatile("griddepcontrol.launch_dependents;" ::: "memory");
    const int k = threadIdx.x;
    if (k < HID) {
        const int rf = 20 + k, rg = 40 + k, ro = 60 + k;
        cw[k]        = 0.5f * W_ih[2 * k];
        cw[20 + k]   = 0.5f * W_ih[2 * k + 1];
        cw[40 + k]   = 0.5f * (b_ih[k] + b_hh[k]);
        cw[60 + k]   = W_ih[2 * rg];
        cw[80 + k]   = W_ih[2 * rg + 1];
        cw[100 + k]  = b_ih[rg] + b_hh[rg];
        cw[120 + k]  = 0.5f * W_ih[2 * ro];
        cw[140 + k]  = 0.5f * W_ih[2 * ro + 1];
        cw[160 + k]  = 0.5f * (b_ih[ro] + b_hh[ro]);
        cw[180 + k]  = 0.5f * W_ih[2 * rf];
        cw[200 + k]  = 0.5f * W_ih[2 * rf + 1];
        cw[220 + k]  = 0.5f * (b_ih[rf] + b_hh[rf]);
        cw[240 + k]  = W_out[k];
    }
    if (k == 0) cw[260] = b_out[0];
}

__device__ __forceinline__ void griddep_wait() {
    asm volatile("griddepcontrol.wait;" ::: "memory");
}

__global__ void __launch_bounds__(NT, 6)
lstm_opt_kernel(const float* __restrict__ params,
                const float* __restrict__ grads,
                const float* __restrict__ h0,
                const float* __restrict__ c0,
                const float* __restrict__ W_hh,   // cold general path
                float* __restrict__ out,
                int n)
{
    const int t    = threadIdx.x;
    const int i    = blockIdx.x * NT + t;
    const int lane = t & 31;

    // Warp's 32-coordinate block: coords [wbase, wbase+32)
    const int wbase = i - lane;
    const bool full_warp = (wbase + 32 <= n);

    if (full_warp) {
        // ---- cW-independent phase: runs BEFORE the PDL wait ----
        const float g = __ldg(&grads[i]);
        const float p = __ldg(&params[i]);

        // Coalesced bitwise-zero scan of the warp's c0 and h0 blocks:
        // interleaved c/h loads with independent OR accumulators -> two
        // address streams, shallow dependency chains, streaming (evict-first)
        // cache policy since these bytes are touched exactly once.
        const uint4* c4 = reinterpret_cast<const uint4*>(c0 + (size_t)wbase * HID);
        const uint4* h4 = reinterpret_cast<const uint4*>(h0 + (size_t)wbase * HID);
        uint32_t orc = 0u, orh = 0u;
        #pragma unroll
        for (int q = 0; q < 5; q++) {
            uint4 vc = __ldcs(&c4[lane + 32 * q]);
            uint4 vh = __ldcs(&h4[lane + 32 * q]);
            orc |= vc.x | vc.y | vc.z | vc.w;
            orh |= vh.x | vh.y | vh.z | vh.w;
        }
        // All bits zero across the warp => every c0/h0 value is +0.0f
        // => f*c0 == 0 and the W_hh matvec is exactly zero. Warp-uniform.
        const bool allzero = __all_sync(0xffffffffu, (orc | orh) == 0u);

        // prep grid's cW writes must be visible beyond this point
        griddep_wait();

        if (__builtin_expect(allzero, 1)) {
            // ---- fast path: no cv, no h; weights are constant-bank operands ----
            float acc = cW[260];
            #pragma unroll
            for (int k = 0; k < HID; k++) {
                float zi = fmaf(cW[k],       g, fmaf(cW[20 + k],  p, cW[40 + k]));  // halved
                float zg = fmaf(cW[60 + k],  g, fmaf(cW[80 + k],  p, cW[100 + k]));
                float zo = fmaf(cW[120 + k], g, fmaf(cW[140 + k], p, cW[160 + k])); // halved

                float ik = sig_from_half(zi);
                float gk = tanh_ap(zg);
                float ok = sig_from_half(zo);

                float c1 = ik * gk;                       // f*c0 == 0, i*g only
                acc = fmaf(ok * tanh_ap(c1), cW[240 + k], acc);
            }
            __stcs(&out[i], acc);
            return;
        }

        // ---- general path (warp-uniform, cold): full LSTM incl. W_hh matvec ----
        float cv[HID], hv[HID];
        {
            const float4* cr = reinterpret_cast<const float4*>(c0 + (size_t)i * HID);
            const float4* hr = reinterpret_cast<const float4*>(h0 + (size_t)i * HID);
            #pragma unroll
            for (int q = 0; q < 5; q++) {
                float4 cc = cr[q];
                cv[4 * q + 0] = cc.x; cv[4 * q + 1] = cc.y;
                cv[4 * q + 2] = cc.z; cv[4 * q + 3] = cc.w;
                float4 hh = hr[q];
                hv[4 * q + 0] = hh.x; hv[4 * q + 1] = hh.y;
                hv[4 * q + 2] = hh.z; hv[4 * q + 3] = hh.w;
            }
        }
        float acc = cW[260];
        #pragma unroll 1
        for (int k = 0; k < HID; k++) {
            float zi = fmaf(cW[k],       g, fmaf(cW[20 + k],  p, cW[40 + k]));
            float zg = fmaf(cW[60 + k],  g, fmaf(cW[80 + k],  p, cW[100 + k]));
            float zo = fmaf(cW[120 + k], g, fmaf(cW[140 + k], p, cW[160 + k]));
            float zf = fmaf(cW[180 + k], g, fmaf(cW[200 + k], p, cW[220 + k]));
            const int ri = k, rf = 20 + k, rg = 40 + k, ro = 60 + k;
            #pragma unroll 1
            for (int m = 0; m < HID; m++) {
                float hm = hv[m];
                zi = fmaf(0.5f * __ldg(&W_hh[ri * HID + m]), hm, zi);
                zf = fmaf(0.5f * __ldg(&W_hh[rf * HID + m]), hm, zf);
                zg = fmaf(       __ldg(&W_hh[rg * HID + m]), hm, zg);
                zo = fmaf(0.5f * __ldg(&W_hh[ro * HID + m]), hm, zo);
            }
            float ik = sig_from_half(zi);
            float fk = sig_from_half(zf);
            float gk = tanh_ap(zg);
            float ok = sig_from_half(zo);
            float c1 = fmaf(fk, cv[k], ik * gk);
            acc = fmaf(ok * tanh_ap(c1), cW[240 + k], acc);
        }
        out[i] = acc;
        return;
    }

    // ---- boundary warp (partial): per-thread general path with guards ----
    if (i >= n) { griddep_wait(); return; }
    {
        const float g = grads[i];
        const float p = params[i];
        float cv[HID], hv[HID];
        #pragma unroll
        for (int m = 0; m < HID; m++) {
            cv[m] = c0[(size_t)i * HID + m];
            hv[m] = h0[(size_t)i * HID + m];
        }
        griddep_wait();
        float acc = cW[260];
        #pragma unroll 1
        for (int k = 0; k < HID; k++) {
            float zi = fmaf(cW[k],       g, fmaf(cW[20 + k],  p, cW[40 + k]));
            float zg = fmaf(cW[60 + k],  g, fmaf(cW[80 + k],  p, cW[100 + k]));
            float zo = fmaf(cW[120 + k], g, fmaf(cW[140 + k], p, cW[160 + k]));
            float zf = fmaf(cW[180 + k], g, fmaf(cW[200 + k], p, cW[220 + k]));
            const int ri = k, rf = 20 + k, rg = 40 + k, ro = 60 + k;
            #pragma unroll 1
            for (int m = 0; m < HID; m++) {
                float hm = hv[m];
                zi = fmaf(0.5f * __ldg(&W_hh[ri * HID + m]), hm, zi);
                zf = fmaf(0.5f * __ldg(&W_hh[rf * HID + m]), hm, zf);
                zg = fmaf(       __ldg(&W_hh[rg * HID + m]), hm, zg);
                zo = fmaf(0.5f * __ldg(&W_hh[ro * HID + m]), hm, zo);
            }
            float ik = sig_from_half(zi);
            float fk = sig_from_half(zf);
            float gk = tanh_ap(zg);
            float ok = sig_from_half(zo);
            float c1 = fmaf(fk, cv[k], ik * gk);
            acc = fmaf(ok * tanh_ap(c1), cW[240 + k], acc);
        }
        out[i] = acc;
    }
}

extern "C" void kernel_launch(void* const* d_in, const int* in_sizes, int n_in,
                              void* d_out, int out_size)
{
    const float* params = (const float*)d_in[0];
    const float* grads  = (const float*)d_in[1];
    const float* h0     = (const float*)d_in[2];
    const float* c0     = (const float*)d_in[3];
    const float* W_ih   = (const float*)d_in[4];
    const float* W_hh   = (const float*)d_in[5];
    const float* b_ih   = (const float*)d_in[6];
    const float* b_hh   = (const float*)d_in[7];
    const float* W_out  = (const float*)d_in[8];
    const float* b_out  = (const float*)d_in[9];
    float* out = (float*)d_out;

    int n = in_sizes[0];

    void* cw_ptr = nullptr;
    cudaGetSymbolAddress(&cw_ptr, cW);     // host-side query, capture-safe
    prep_kernel<<<1, 32>>>(W_ih, b_ih, b_hh, W_out, b_out, (float*)cw_ptr);

    // Main kernel with Programmatic Stream Serialization: launches while prep
    // is still executing; griddepcontrol.wait inside orders cW consumption.
    int blocks = (n + NT - 1) / NT;

    cudaLaunchConfig_t cfg = {};
    cfg.gridDim  = dim3((unsigned)blocks, 1, 1);
    cfg.blockDim = dim3(NT, 1, 1);
    cfg.dynamicSmemBytes = 0;
    cfg.stream = 0;
    cudaLaunchAttribute attrs[1];
    attrs[0].id = cudaLaunchAttributeProgrammaticStreamSerialization;
    attrs[0].val.programmaticStreamSerializationAllowed = 1;
    cfg.attrs = attrs;
    cfg.numAttrs = 1;

    cudaLaunchKernelEx(&cfg, lstm_opt_kernel,
                       params, grads, h0, c0, W_hh, out, n);
}